// round 2
// baseline (speedup 1.0000x reference)
#include <cuda_runtime.h>
#include <math.h>

#define BB 2
#define TT 2048
#define CC 768
#define HH 12
#define DD 64
#define M1 (BB*TT)      /* 4096 */
#define N1 (3*CC)       /* 2304 */

// Scratch (allocation-free rule: __device__ globals)
__device__ float g_q[(size_t)BB*HH*TT*DD];
__device__ float g_k[(size_t)BB*HH*TT*DD];
__device__ float g_v[(size_t)BB*HH*TT*DD];
__device__ float g_att[(size_t)BB*TT*CC];

// ---------------------------------------------------------------------------
// QKV GEMM: qkv[M1, N1] = x[M1, CC] @ W[CC, N1] + b, scattered to Q/K/V [B,H,T,D]
// 64x64 tile, 256 threads, 4x4 micro-tile, K-tile 16
// ---------------------------------------------------------------------------
__global__ __launch_bounds__(256) void qkv_gemm_kernel(
    const float* __restrict__ x, const float* __restrict__ W,
    const float* __restrict__ bias)
{
    __shared__ float As[16][65];
    __shared__ float Bs[16][64];
    const int tx = threadIdx.x & 15;
    const int ty = threadIdx.x >> 4;
    const int m0 = blockIdx.y * 64;
    const int n0 = blockIdx.x * 64;

    float acc[4][4];
#pragma unroll
    for (int i = 0; i < 4; i++)
#pragma unroll
        for (int j = 0; j < 4; j++) acc[i][j] = 0.f;

    const int am = threadIdx.x >> 2;         // 0..63
    const int ak = (threadIdx.x & 3) << 2;   // 0,4,8,12
    const int bk = threadIdx.x >> 4;         // 0..15
    const int bn = (threadIdx.x & 15) << 2;  // 0..60

    for (int k0 = 0; k0 < CC; k0 += 16) {
        float4 av = *(const float4*)(x + (size_t)(m0 + am) * CC + k0 + ak);
        As[ak + 0][am] = av.x; As[ak + 1][am] = av.y;
        As[ak + 2][am] = av.z; As[ak + 3][am] = av.w;
        float4 bv = *(const float4*)(W + (size_t)(k0 + bk) * N1 + n0 + bn);
        *(float4*)&Bs[bk][bn] = bv;
        __syncthreads();
#pragma unroll
        for (int kk = 0; kk < 16; kk++) {
            float a0 = As[kk][ty * 4 + 0];
            float a1 = As[kk][ty * 4 + 1];
            float a2 = As[kk][ty * 4 + 2];
            float a3 = As[kk][ty * 4 + 3];
            float4 b4 = *(const float4*)&Bs[kk][tx * 4];
            acc[0][0] += a0 * b4.x; acc[0][1] += a0 * b4.y; acc[0][2] += a0 * b4.z; acc[0][3] += a0 * b4.w;
            acc[1][0] += a1 * b4.x; acc[1][1] += a1 * b4.y; acc[1][2] += a1 * b4.z; acc[1][3] += a1 * b4.w;
            acc[2][0] += a2 * b4.x; acc[2][1] += a2 * b4.y; acc[2][2] += a2 * b4.z; acc[2][3] += a2 * b4.w;
            acc[3][0] += a3 * b4.x; acc[3][1] += a3 * b4.y; acc[3][2] += a3 * b4.z; acc[3][3] += a3 * b4.w;
        }
        __syncthreads();
    }

    // Epilogue: whole 64-wide tile falls in one of {q,k,v} and one head
    const int which = n0 / CC;               // 0=q, 1=k, 2=v
    float* dst = (which == 0) ? g_q : (which == 1) ? g_k : g_v;
    const int h = (n0 % CC) / DD;
    float b0v = bias[n0 + tx * 4 + 0];
    float b1v = bias[n0 + tx * 4 + 1];
    float b2v = bias[n0 + tx * 4 + 2];
    float b3v = bias[n0 + tx * 4 + 3];
#pragma unroll
    for (int i = 0; i < 4; i++) {
        const int mrow = m0 + ty * 4 + i;
        const int b = mrow / TT;
        const int t = mrow % TT;
        float* rowp = dst + (((size_t)b * HH + h) * TT + t) * DD + tx * 4;
        float4 r;
        r.x = acc[i][0] + b0v; r.y = acc[i][1] + b1v;
        r.z = acc[i][2] + b2v; r.w = acc[i][3] + b3v;
        *(float4*)rowp = r;
    }
}

// ---------------------------------------------------------------------------
// Flash-style causal attention. One block per (b*h, 64-query tile).
// 64 threads; each thread owns one query row: q[64], o[64] in registers.
// Online softmax with branch-optimized rescale. Non-diagonal, fully-unmasked
// tiles run a branch-free inner loop.
// ---------------------------------------------------------------------------
__global__ __launch_bounds__(64) void attn_kernel(const int* __restrict__ mask)
{
    const int bh   = blockIdx.y;          // b*HH + h
    const int b    = bh / HH;
    const int h    = bh % HH;
    const int qblk = blockIdx.x;
    const int tid  = threadIdx.x;
    const int qrow = qblk * 64 + tid;

    const float* Qp = g_q + ((size_t)bh * TT + qrow) * DD;
    float q[DD];
#pragma unroll
    for (int d = 0; d < DD; d++) q[d] = Qp[d] * 0.125f;   // fold 1/sqrt(64)

    float o[DD];
#pragma unroll
    for (int d = 0; d < DD; d++) o[d] = 0.f;
    float m = -INFINITY, l = 0.f;

    __shared__ float Ks[64][DD];
    __shared__ float Vs[64][DD];
    __shared__ int   Ms[64];
    __shared__ int   tile_all_ones;

    const int diagj0 = qblk * 64;
    for (int j0 = 0; j0 <= diagj0; j0 += 64) {
        const float* Kg = g_k + ((size_t)bh * TT + j0) * DD;
        const float* Vg = g_v + ((size_t)bh * TT + j0) * DD;
        __syncthreads();
#pragma unroll 8
        for (int i = 0; i < 64; i++) {
            Ks[i][tid] = Kg[i * DD + tid];
            Vs[i][tid] = Vg[i * DD + tid];
        }
        int mv = mask[b * TT + j0 + tid];
        Ms[tid] = mv;
        // all-ones tile detection (two warps): warp-and then combine
        unsigned ball = __ballot_sync(0xFFFFFFFFu, mv != 0);
        if ((tid & 31) == 0) {
            if (tid == 0) tile_all_ones = 1;
        }
        __syncthreads();
        if ((tid & 31) == 0 && ball != 0xFFFFFFFFu) tile_all_ones = 0;
        __syncthreads();

        const bool diag = (j0 == diagj0);
        if (!diag && tile_all_ones) {
            // Branch-free hot path
            for (int j = 0; j < 64; j++) {
                float s = 0.f;
#pragma unroll
                for (int d = 0; d < DD; d++) s += q[d] * Ks[j][d];
                if (s <= m) {
                    float p = __expf(s - m);
                    l += p;
#pragma unroll
                    for (int d = 0; d < DD; d++) o[d] += p * Vs[j][d];
                } else {
                    float corr = __expf(m - s);
                    m = s;
                    l = l * corr + 1.f;
#pragma unroll
                    for (int d = 0; d < DD; d++) o[d] = o[d] * corr + Vs[j][d];
                }
            }
        } else {
            for (int j = 0; j < 64; j++) {
                if (diag && (j0 + j) > qrow) break;   // causal: keys ascending
                if (Ms[j] == 0) continue;             // attention_mask == 0 -> -inf
                float s = 0.f;
#pragma unroll
                for (int d = 0; d < DD; d++) s += q[d] * Ks[j][d];
                if (s <= m) {
                    float p = __expf(s - m);
                    l += p;
#pragma unroll
                    for (int d = 0; d < DD; d++) o[d] += p * Vs[j][d];
                } else {
                    float corr = __expf(m - s);
                    m = s;
                    l = l * corr + 1.f;
#pragma unroll
                    for (int d = 0; d < DD; d++) o[d] = o[d] * corr + Vs[j][d];
                }
            }
        }
    }

    const float inv = 1.f / l;
    float* outp = g_att + ((size_t)b * TT + qrow) * CC + h * DD;
#pragma unroll
    for (int d = 0; d < DD; d++) outp[d] = o[d] * inv;
}

// ---------------------------------------------------------------------------
// Proj GEMM: out[M1, CC] = g_att[M1, CC] @ W_proj[CC, CC] + b_proj
// ---------------------------------------------------------------------------
__global__ __launch_bounds__(256) void proj_gemm_kernel(
    const float* __restrict__ W, const float* __restrict__ bias,
    float* __restrict__ out)
{
    __shared__ float As[16][65];
    __shared__ float Bs[16][64];
    const int tx = threadIdx.x & 15;
    const int ty = threadIdx.x >> 4;
    const int m0 = blockIdx.y * 64;
    const int n0 = blockIdx.x * 64;

    float acc[4][4];
#pragma unroll
    for (int i = 0; i < 4; i++)
#pragma unroll
        for (int j = 0; j < 4; j++) acc[i][j] = 0.f;

    const int am = threadIdx.x >> 2;
    const int ak = (threadIdx.x & 3) << 2;
    const int bk = threadIdx.x >> 4;
    const int bn = (threadIdx.x & 15) << 2;

    for (int k0 = 0; k0 < CC; k0 += 16) {
        float4 av = *(const float4*)(g_att + (size_t)(m0 + am) * CC + k0 + ak);
        As[ak + 0][am] = av.x; As[ak + 1][am] = av.y;
        As[ak + 2][am] = av.z; As[ak + 3][am] = av.w;
        float4 bv = *(const float4*)(W + (size_t)(k0 + bk) * CC + n0 + bn);
        *(float4*)&Bs[bk][bn] = bv;
        __syncthreads();
#pragma unroll
        for (int kk = 0; kk < 16; kk++) {
            float a0 = As[kk][ty * 4 + 0];
            float a1 = As[kk][ty * 4 + 1];
            float a2 = As[kk][ty * 4 + 2];
            float a3 = As[kk][ty * 4 + 3];
            float4 b4 = *(const float4*)&Bs[kk][tx * 4];
            acc[0][0] += a0 * b4.x; acc[0][1] += a0 * b4.y; acc[0][2] += a0 * b4.z; acc[0][3] += a0 * b4.w;
            acc[1][0] += a1 * b4.x; acc[1][1] += a1 * b4.y; acc[1][2] += a1 * b4.z; acc[1][3] += a1 * b4.w;
            acc[2][0] += a2 * b4.x; acc[2][1] += a2 * b4.y; acc[2][2] += a2 * b4.z; acc[2][3] += a2 * b4.w;
            acc[3][0] += a3 * b4.x; acc[3][1] += a3 * b4.y; acc[3][2] += a3 * b4.z; acc[3][3] += a3 * b4.w;
        }
        __syncthreads();
    }

    float b0v = bias[n0 + tx * 4 + 0];
    float b1v = bias[n0 + tx * 4 + 1];
    float b2v = bias[n0 + tx * 4 + 2];
    float b3v = bias[n0 + tx * 4 + 3];
#pragma unroll
    for (int i = 0; i < 4; i++) {
        const int mrow = m0 + ty * 4 + i;
        float4 r;
        r.x = acc[i][0] + b0v; r.y = acc[i][1] + b1v;
        r.z = acc[i][2] + b2v; r.w = acc[i][3] + b3v;
        *(float4*)(out + (size_t)mrow * CC + n0 + tx * 4) = r;
    }
}

extern "C" void kernel_launch(void* const* d_in, const int* in_sizes, int n_in,
                              void* d_out, int out_size)
{
    const float* x      = (const float*)d_in[0];
    const int*   mask   = (const int*)  d_in[1];
    const float* W_attn = (const float*)d_in[2];
    const float* b_attn = (const float*)d_in[3];
    const float* W_proj = (const float*)d_in[4];
    const float* b_proj = (const float*)d_in[5];
    float* out = (float*)d_out;

    dim3 g1(N1 / 64, M1 / 64);   // (36, 64)
    qkv_gemm_kernel<<<g1, 256>>>(x, W_attn, b_attn);

    dim3 g2(TT / 64, BB * HH);   // (32, 24)
    attn_kernel<<<g2, 64>>>(mask);

    dim3 g3(CC / 64, M1 / 64);   // (12, 64)
    proj_gemm_kernel<<<g3, 256>>>(W_proj, b_proj, out);
}

// round 5
// speedup vs baseline: 1.6519x; 1.6519x over previous
#include <cuda_runtime.h>
#include <cuda_bf16.h>
#include <math.h>

#define BB 2
#define TT 2048
#define CC 768
#define HH 12
#define DD 64
#define M1 (BB*TT)      /* 4096 */
#define N1 (3*CC)       /* 2304 */

// Scratch (allocation-free rule: __device__ globals)
__device__ float g_q[(size_t)BB*HH*TT*DD];
__device__ float g_k[(size_t)BB*HH*TT*DD];
__device__ float g_v[(size_t)BB*HH*TT*DD];
__device__ float g_att[(size_t)BB*TT*CC];

// ---------------------------------------------------------------------------
// MMA helpers
// ---------------------------------------------------------------------------
__device__ __forceinline__ void mma_tf32_16x8x8(float* c, const unsigned* a,
                                                unsigned b0, unsigned b1) {
    asm volatile(
        "mma.sync.aligned.m16n8k8.row.col.f32.tf32.tf32.f32 "
        "{%0,%1,%2,%3}, {%4,%5,%6,%7}, {%8,%9}, {%0,%1,%2,%3};\n"
        : "+f"(c[0]), "+f"(c[1]), "+f"(c[2]), "+f"(c[3])
        : "r"(a[0]), "r"(a[1]), "r"(a[2]), "r"(a[3]), "r"(b0), "r"(b1));
}

__device__ __forceinline__ void mma_bf16_16x8x16(float* c, const unsigned* a,
                                                 unsigned b0, unsigned b1) {
    asm volatile(
        "mma.sync.aligned.m16n8k16.row.col.f32.bf16.bf16.f32 "
        "{%0,%1,%2,%3}, {%4,%5,%6,%7}, {%8,%9}, {%0,%1,%2,%3};\n"
        : "+f"(c[0]), "+f"(c[1]), "+f"(c[2]), "+f"(c[3])
        : "r"(a[0]), "r"(a[1]), "r"(a[2]), "r"(a[3]), "r"(b0), "r"(b1));
}

__device__ __forceinline__ unsigned f2tf32(float x) {
    unsigned r;
    asm("cvt.rna.tf32.f32 %0, %1;" : "=r"(r) : "f"(x));
    return r;
}

// ---------------------------------------------------------------------------
// QKV GEMM: qkv[M1, N1] = x[M1, CC] @ W[CC, N1] + b, scattered to Q/K/V [B,H,T,D]
// ---------------------------------------------------------------------------
__global__ __launch_bounds__(256) void qkv_gemm_kernel(
    const float* __restrict__ x, const float* __restrict__ W,
    const float* __restrict__ bias)
{
    __shared__ float As[16][65];
    __shared__ float Bs[16][64];
    const int tx = threadIdx.x & 15;
    const int ty = threadIdx.x >> 4;
    const int m0 = blockIdx.y * 64;
    const int n0 = blockIdx.x * 64;

    float acc[4][4];
#pragma unroll
    for (int i = 0; i < 4; i++)
#pragma unroll
        for (int j = 0; j < 4; j++) acc[i][j] = 0.f;

    const int am = threadIdx.x >> 2;
    const int ak = (threadIdx.x & 3) << 2;
    const int bk = threadIdx.x >> 4;
    const int bn = (threadIdx.x & 15) << 2;

    for (int k0 = 0; k0 < CC; k0 += 16) {
        float4 av = *(const float4*)(x + (size_t)(m0 + am) * CC + k0 + ak);
        As[ak + 0][am] = av.x; As[ak + 1][am] = av.y;
        As[ak + 2][am] = av.z; As[ak + 3][am] = av.w;
        float4 bv = *(const float4*)(W + (size_t)(k0 + bk) * N1 + n0 + bn);
        *(float4*)&Bs[bk][bn] = bv;
        __syncthreads();
#pragma unroll
        for (int kk = 0; kk < 16; kk++) {
            float a0 = As[kk][ty * 4 + 0];
            float a1 = As[kk][ty * 4 + 1];
            float a2 = As[kk][ty * 4 + 2];
            float a3 = As[kk][ty * 4 + 3];
            float4 b4 = *(const float4*)&Bs[kk][tx * 4];
            acc[0][0] += a0 * b4.x; acc[0][1] += a0 * b4.y; acc[0][2] += a0 * b4.z; acc[0][3] += a0 * b4.w;
            acc[1][0] += a1 * b4.x; acc[1][1] += a1 * b4.y; acc[1][2] += a1 * b4.z; acc[1][3] += a1 * b4.w;
            acc[2][0] += a2 * b4.x; acc[2][1] += a2 * b4.y; acc[2][2] += a2 * b4.z; acc[2][3] += a2 * b4.w;
            acc[3][0] += a3 * b4.x; acc[3][1] += a3 * b4.y; acc[3][2] += a3 * b4.z; acc[3][3] += a3 * b4.w;
        }
        __syncthreads();
    }

    const int which = n0 / CC;
    float* dst = (which == 0) ? g_q : (which == 1) ? g_k : g_v;
    const int h = (n0 % CC) / DD;
    float b0v = bias[n0 + tx * 4 + 0];
    float b1v = bias[n0 + tx * 4 + 1];
    float b2v = bias[n0 + tx * 4 + 2];
    float b3v = bias[n0 + tx * 4 + 3];
#pragma unroll
    for (int i = 0; i < 4; i++) {
        const int mrow = m0 + ty * 4 + i;
        const int b = mrow / TT;
        const int t = mrow % TT;
        float* rowp = dst + (((size_t)b * HH + h) * TT + t) * DD + tx * 4;
        float4 r;
        r.x = acc[i][0] + b0v; r.y = acc[i][1] + b1v;
        r.z = acc[i][2] + b2v; r.w = acc[i][3] + b3v;
        *(float4*)rowp = r;
    }
}

// ---------------------------------------------------------------------------
// FlashAttention-2 style attention with mma.sync tensor cores.
// QK^T in tf32 (m16n8k8). P*V in SPLIT bf16 (3-mma compensated product):
//   O += Ph*Vh + Pl*Vh + Ph*Vl   (drops only Pl*Vl ~ 2^-18)
// Row max AND row sum quad-reduced via shfl.
// ---------------------------------------------------------------------------
__global__ __launch_bounds__(128) void attn_mma_kernel(const int* __restrict__ mask)
{
    const int bh   = blockIdx.y;
    const int b    = bh / HH;
    const int h    = bh % HH;
    const int qblk = blockIdx.x;
    const int tid  = threadIdx.x;
    const int warp = tid >> 5;
    const int lane = tid & 31;
    const int g    = lane >> 2;
    const int qr   = lane & 3;

    __shared__ float          Ks[64][68];
    __shared__ __nv_bfloat16  Vth[64][72];   // [dim][key] hi part
    __shared__ __nv_bfloat16  Vtl[64][72];   // [dim][key] lo part
    __shared__ int            Ms[64];

    // ---- stage Q tile into Ks, preload A fragments (tf32, scaled by 1/8) ----
    {
        const float* Qg = g_q + ((size_t)bh * TT + qblk * 64) * DD;
        int row = tid >> 1, cb = (tid & 1) * 32;
        const float4* src = (const float4*)(Qg + row * DD + cb);
        float4* dstp = (float4*)&Ks[row][cb];
#pragma unroll
        for (int i = 0; i < 8; i++) dstp[i] = src[i];
    }
    __syncthreads();

    unsigned qf[8][4];
    {
        const int r0 = warp * 16 + g;
#pragma unroll
        for (int k = 0; k < 8; k++) {
            qf[k][0] = f2tf32(Ks[r0    ][k * 8 + qr    ] * 0.125f);
            qf[k][1] = f2tf32(Ks[r0 + 8][k * 8 + qr    ] * 0.125f);
            qf[k][2] = f2tf32(Ks[r0    ][k * 8 + qr + 4] * 0.125f);
            qf[k][3] = f2tf32(Ks[r0 + 8][k * 8 + qr + 4] * 0.125f);
        }
    }

    float oacc[8][4];
#pragma unroll
    for (int n = 0; n < 8; n++)
#pragma unroll
        for (int i = 0; i < 4; i++) oacc[n][i] = 0.f;
    float m0r = -1e30f, m1r = -1e30f;
    float l0r = 0.f,    l1r = 0.f;

    const int qrow0 = qblk * 64 + warp * 16 + g;
    const int qrow1 = qrow0 + 8;
    const int jend  = qblk * 64;

    for (int j0 = 0; j0 <= jend; j0 += 64) {
        __syncthreads();
        // ---- load K tile (fp32) and V tile (split bf16, transposed) ----
        {
            int row = tid >> 1, cb = (tid & 1) * 32;
            const float4* ks = (const float4*)(g_k + ((size_t)bh * TT + j0 + row) * DD + cb);
            float4* kd = (float4*)&Ks[row][cb];
#pragma unroll
            for (int i = 0; i < 8; i++) kd[i] = ks[i];
            const float4* vs = (const float4*)(g_v + ((size_t)bh * TT + j0 + row) * DD + cb);
#pragma unroll
            for (int i = 0; i < 8; i++) {
                float4 v = vs[i];
                float vv[4] = {v.x, v.y, v.z, v.w};
#pragma unroll
                for (int e = 0; e < 4; e++) {
                    __nv_bfloat16 hi = __float2bfloat16(vv[e]);
                    __nv_bfloat16 lo = __float2bfloat16(vv[e] - __bfloat162float(hi));
                    Vth[cb + i * 4 + e][row] = hi;
                    Vtl[cb + i * 4 + e][row] = lo;
                }
            }
        }
        if (tid < 64) Ms[tid] = mask[b * TT + j0 + tid];
        __syncthreads();

        // ---- S = Q @ K^T (tf32) ----
        float sacc[8][4];
#pragma unroll
        for (int n = 0; n < 8; n++)
#pragma unroll
            for (int i = 0; i < 4; i++) sacc[n][i] = 0.f;

#pragma unroll
        for (int k = 0; k < 8; k++) {
#pragma unroll
            for (int n = 0; n < 8; n++) {
                unsigned b0 = __float_as_uint(Ks[n * 8 + g][k * 8 + qr    ]);
                unsigned b1 = __float_as_uint(Ks[n * 8 + g][k * 8 + qr + 4]);
                mma_tf32_16x8x8(sacc[n], qf[k], b0, b1);
            }
        }

        // ---- masking ----
        const bool diag = (j0 == jend);
#pragma unroll
        for (int n = 0; n < 8; n++) {
            int c0 = n * 8 + qr * 2;
            int gc0 = j0 + c0;
            if (Ms[c0] == 0)     { sacc[n][0] = -1e30f; sacc[n][2] = -1e30f; }
            if (Ms[c0 + 1] == 0) { sacc[n][1] = -1e30f; sacc[n][3] = -1e30f; }
            if (diag) {
                if (gc0     > qrow0) sacc[n][0] = -1e30f;
                if (gc0 + 1 > qrow0) sacc[n][1] = -1e30f;
                if (gc0     > qrow1) sacc[n][2] = -1e30f;
                if (gc0 + 1 > qrow1) sacc[n][3] = -1e30f;
            }
        }

        // ---- online softmax (max AND sum quad-reduced) ----
        float tm0 = -1e30f, tm1 = -1e30f;
#pragma unroll
        for (int n = 0; n < 8; n++) {
            tm0 = fmaxf(tm0, fmaxf(sacc[n][0], sacc[n][1]));
            tm1 = fmaxf(tm1, fmaxf(sacc[n][2], sacc[n][3]));
        }
        tm0 = fmaxf(tm0, __shfl_xor_sync(0xFFFFFFFFu, tm0, 1));
        tm0 = fmaxf(tm0, __shfl_xor_sync(0xFFFFFFFFu, tm0, 2));
        tm1 = fmaxf(tm1, __shfl_xor_sync(0xFFFFFFFFu, tm1, 1));
        tm1 = fmaxf(tm1, __shfl_xor_sync(0xFFFFFFFFu, tm1, 2));

        float nm0 = fmaxf(m0r, tm0);
        float nm1 = fmaxf(m1r, tm1);
        float corr0 = __expf(m0r - nm0);
        float corr1 = __expf(m1r - nm1);
        m0r = nm0; m1r = nm1;

        unsigned pAh[4][4], pAl[4][4];
        float rs0 = 0.f, rs1 = 0.f;
#pragma unroll
        for (int n = 0; n < 8; n++) {
            float p0 = __expf(sacc[n][0] - nm0);
            float p1 = __expf(sacc[n][1] - nm0);
            float p2 = __expf(sacc[n][2] - nm1);
            float p3 = __expf(sacc[n][3] - nm1);
            rs0 += p0 + p1;
            rs1 += p2 + p3;
            // split each p into bf16 hi + bf16 lo
            __nv_bfloat16 h0 = __float2bfloat16(p0), h1 = __float2bfloat16(p1);
            __nv_bfloat16 h2 = __float2bfloat16(p2), h3 = __float2bfloat16(p3);
            __nv_bfloat162 hlo = {h0, h1}, hhi = {h2, h3};
            __nv_bfloat162 llo = {__float2bfloat16(p0 - __bfloat162float(h0)),
                                  __float2bfloat16(p1 - __bfloat162float(h1))};
            __nv_bfloat162 lhi = {__float2bfloat16(p2 - __bfloat162float(h2)),
                                  __float2bfloat16(p3 - __bfloat162float(h3))};
            unsigned uhlo = *(unsigned*)&hlo, uhhi = *(unsigned*)&hhi;
            unsigned ullo = *(unsigned*)&llo, ulhi = *(unsigned*)&lhi;
            if ((n & 1) == 0) {
                pAh[n >> 1][0] = uhlo; pAh[n >> 1][1] = uhhi;
                pAl[n >> 1][0] = ullo; pAl[n >> 1][1] = ulhi;
            } else {
                pAh[n >> 1][2] = uhlo; pAh[n >> 1][3] = uhhi;
                pAl[n >> 1][2] = ullo; pAl[n >> 1][3] = ulhi;
            }
        }
        // row sum spans the quad -> reduce partial sums
        rs0 += __shfl_xor_sync(0xFFFFFFFFu, rs0, 1);
        rs0 += __shfl_xor_sync(0xFFFFFFFFu, rs0, 2);
        rs1 += __shfl_xor_sync(0xFFFFFFFFu, rs1, 1);
        rs1 += __shfl_xor_sync(0xFFFFFFFFu, rs1, 2);

        l0r = l0r * corr0 + rs0;
        l1r = l1r * corr1 + rs1;
#pragma unroll
        for (int n = 0; n < 8; n++) {
            oacc[n][0] *= corr0; oacc[n][1] *= corr0;
            oacc[n][2] *= corr1; oacc[n][3] *= corr1;
        }

        // ---- O += Ph*Vh + Pl*Vh + Ph*Vl (split bf16) ----
#pragma unroll
        for (int c = 0; c < 4; c++) {
#pragma unroll
            for (int d = 0; d < 8; d++) {
                unsigned bh0 = *(const unsigned*)&Vth[d * 8 + g][c * 16 + qr * 2    ];
                unsigned bh1 = *(const unsigned*)&Vth[d * 8 + g][c * 16 + qr * 2 + 8];
                unsigned bl0 = *(const unsigned*)&Vtl[d * 8 + g][c * 16 + qr * 2    ];
                unsigned bl1 = *(const unsigned*)&Vtl[d * 8 + g][c * 16 + qr * 2 + 8];
                mma_bf16_16x8x16(oacc[d], pAh[c], bh0, bh1);
                mma_bf16_16x8x16(oacc[d], pAl[c], bh0, bh1);
                mma_bf16_16x8x16(oacc[d], pAh[c], bl0, bl1);
            }
        }
    }

    // ---- epilogue ----
    const float inv0 = 1.f / l0r;
    const float inv1 = 1.f / l1r;
    float* base0 = g_att + ((size_t)b * TT + qrow0) * CC + h * DD;
    float* base1 = g_att + ((size_t)b * TT + qrow1) * CC + h * DD;
#pragma unroll
    for (int n = 0; n < 8; n++) {
        int dcol = n * 8 + qr * 2;
        float2 r0; r0.x = oacc[n][0] * inv0; r0.y = oacc[n][1] * inv0;
        float2 r1; r1.x = oacc[n][2] * inv1; r1.y = oacc[n][3] * inv1;
        *(float2*)(base0 + dcol) = r0;
        *(float2*)(base1 + dcol) = r1;
    }
}

// ---------------------------------------------------------------------------
// Proj GEMM: out[M1, CC] = g_att[M1, CC] @ W_proj[CC, CC] + b_proj
// ---------------------------------------------------------------------------
__global__ __launch_bounds__(256) void proj_gemm_kernel(
    const float* __restrict__ W, const float* __restrict__ bias,
    float* __restrict__ out)
{
    __shared__ float As[16][65];
    __shared__ float Bs[16][64];
    const int tx = threadIdx.x & 15;
    const int ty = threadIdx.x >> 4;
    const int m0 = blockIdx.y * 64;
    const int n0 = blockIdx.x * 64;

    float acc[4][4];
#pragma unroll
    for (int i = 0; i < 4; i++)
#pragma unroll
        for (int j = 0; j < 4; j++) acc[i][j] = 0.f;

    const int am = threadIdx.x >> 2;
    const int ak = (threadIdx.x & 3) << 2;
    const int bk = threadIdx.x >> 4;
    const int bn = (threadIdx.x & 15) << 2;

    for (int k0 = 0; k0 < CC; k0 += 16) {
        float4 av = *(const float4*)(g_att + (size_t)(m0 + am) * CC + k0 + ak);
        As[ak + 0][am] = av.x; As[ak + 1][am] = av.y;
        As[ak + 2][am] = av.z; As[ak + 3][am] = av.w;
        float4 bv = *(const float4*)(W + (size_t)(k0 + bk) * CC + n0 + bn);
        *(float4*)&Bs[bk][bn] = bv;
        __syncthreads();
#pragma unroll
        for (int kk = 0; kk < 16; kk++) {
            float a0 = As[kk][ty * 4 + 0];
            float a1 = As[kk][ty * 4 + 1];
            float a2 = As[kk][ty * 4 + 2];
            float a3 = As[kk][ty * 4 + 3];
            float4 b4 = *(const float4*)&Bs[kk][tx * 4];
            acc[0][0] += a0 * b4.x; acc[0][1] += a0 * b4.y; acc[0][2] += a0 * b4.z; acc[0][3] += a0 * b4.w;
            acc[1][0] += a1 * b4.x; acc[1][1] += a1 * b4.y; acc[1][2] += a1 * b4.z; acc[1][3] += a1 * b4.w;
            acc[2][0] += a2 * b4.x; acc[2][1] += a2 * b4.y; acc[2][2] += a2 * b4.z; acc[2][3] += a2 * b4.w;
            acc[3][0] += a3 * b4.x; acc[3][1] += a3 * b4.y; acc[3][2] += a3 * b4.z; acc[3][3] += a3 * b4.w;
        }
        __syncthreads();
    }

    float b0v = bias[n0 + tx * 4 + 0];
    float b1v = bias[n0 + tx * 4 + 1];
    float b2v = bias[n0 + tx * 4 + 2];
    float b3v = bias[n0 + tx * 4 + 3];
#pragma unroll
    for (int i = 0; i < 4; i++) {
        const int mrow = m0 + ty * 4 + i;
        float4 r;
        r.x = acc[i][0] + b0v; r.y = acc[i][1] + b1v;
        r.z = acc[i][2] + b2v; r.w = acc[i][3] + b3v;
        *(float4*)(out + (size_t)mrow * CC + n0 + tx * 4) = r;
    }
}

extern "C" void kernel_launch(void* const* d_in, const int* in_sizes, int n_in,
                              void* d_out, int out_size)
{
    const float* x      = (const float*)d_in[0];
    const int*   mask   = (const int*)  d_in[1];
    const float* W_attn = (const float*)d_in[2];
    const float* b_attn = (const float*)d_in[3];
    const float* W_proj = (const float*)d_in[4];
    const float* b_proj = (const float*)d_in[5];
    float* out = (float*)d_out;

    dim3 g1(N1 / 64, M1 / 64);   // (36, 64)
    qkv_gemm_kernel<<<g1, 256>>>(x, W_attn, b_attn);

    dim3 g2(TT / 64, BB * HH);   // (32, 24)
    attn_mma_kernel<<<g2, 128>>>(mask);

    dim3 g3(CC / 64, M1 / 64);   // (12, 64)
    proj_gemm_kernel<<<g3, 256>>>(W_proj, b_proj, out);
}